// round 9
// baseline (speedup 1.0000x reference)
#include <cuda_runtime.h>
#include <cuda_bf16.h>

#define BD 5376
#define CHB 0
#define PNB 128
#define DNB 256
#define ATT_SUM 384
#define ATT_SQ 385
#define PIF 3.14159265358979323846f

typedef unsigned long long ULL;
union F2U { ULL u; float2 f; };

__device__ float g_BE[65536], g_BO[65536], g_BPe[65536], g_BPo[65536];
__device__ float g_ce[256], g_co[256], g_attcoef[512];
__device__ float g_Wfold[49152], g_biasL[96], g_Mpatch[8192], g_bias2[512];
__device__ float g_xt[BD*512], g_xs[BD*256], g_xd[BD*256];
__device__ float g_zsplit[BD*512], g_u[BD*256], g_v[BD*256], g_z1[BD*512], g_z2[BD*512];
__device__ float g_zres[BD*96], g_h[BD*96];
__device__ float g_energy[BD], g_norme[BD], g_att[BD], g_att1[BD];
__device__ float g_thr[2], g_stats[512];

__device__ __forceinline__ float gelu_f(float x){
    return 0.5f*x*(1.0f+erff(x*0.70710678118654752440f));
}
__device__ __forceinline__ ULL dup2(float x){ ULL r; asm("mov.b64 %0,{%1,%1};":"=l"(r):"f"(x)); return r; }
#define FFMA2(d,a,b) asm("fma.rn.f32x2 %0, %1, %2, %0;" : "+l"(d) : "l"(a), "l"(b))

// ---- DCT matrices + attcoef + stats zero + biasL init ----
__global__ void k_mats(const float* __restrict__ adw, const float* __restrict__ bl){
    int bm = blockIdx.x, t = threadIdx.x;
    if(bm < 256){
        int m = bm, j = t;
        float am = PIF*(float)(2*m+1);
        float ce = cosf(am*(float)(2*j)*(1.0f/1024.0f));
        float co = cosf(am*(float)(2*j+1)*(1.0f/1024.0f));
        g_BE[m*256+j] = 2.0f*ce;
        g_BO[m*256+j] = 2.0f*co;
        float bpe = ce*((j==0)?0.5f:1.0f)*(1.0f/512.0f);
        float bpo = co*(1.0f/512.0f);
        g_BPe[j*256+m] = bpe;
        g_BPo[j*256+m] = bpo;
        __shared__ float r1[256], r2[256];
        r1[t]=bpe; r2[t]=bpo; __syncthreads();
        for(int o=128;o>0;o>>=1){ if(t<o){ r1[t]+=r1[t+o]; r2[t]+=r2[t+o]; } __syncthreads(); }
        if(t==0){ g_ce[m]=r1[0]; g_co[m]=r2[0]; }
    } else {
        float rL = sqrtf(512.0f);
        for(int m=t; m<512; m+=256){
            float am = PIF*(float)(2*m+1);
            float s = 0.f;
            for(int k=0;k<5;k++){
                float c = 2.0f*cosf(am*(float)k*(1.0f/1024.0f));
                float so = (k==0)? (0.5f/rL) : (0.5f*sqrtf(2.0f)/rL);
                s += adw[k]*so*c;
            }
            g_attcoef[m]=s;
        }
        g_stats[t]=0.f; g_stats[t+256]=0.f;
        if(t<96) g_biasL[t]=bl[t];
    }
}

// ---- fold1: Wfold + biasL ----
__global__ __launch_bounds__(256) void k_fold1n(const float* __restrict__ We,
        const float* __restrict__ Wl, const float* __restrict__ be){
    __shared__ float sWe[4096];
    __shared__ float sbe[256];
    __shared__ float sWl[32][100];
    int n = blockIdx.x, tid = threadIdx.x;
    for(int i=tid;i<4096;i+=256) sWe[i]=We[i];
    sbe[tid]=be[tid];
    int pp = tid>>5, ts = tid&31;
    float acc[2][3] = {};
    float accb = 0.f;
    for(int k0=0;k0<256;k0+=32){
        __syncthreads();
        for(int i2=tid;i2<32*96;i2+=256){
            int r=i2/96, c2=i2-r*96;
            sWl[r][c2]=Wl[(size_t)(n*256+k0+r)*96+c2];
        }
        __syncthreads();
        #pragma unroll
        for(int kk=0;kk<32;kk++){
            float a0=sWe[pp*256+k0+kk], a1=sWe[(pp+8)*256+k0+kk];
            float b0=sWl[kk][ts], b1=sWl[kk][ts+32], b2=sWl[kk][ts+64];
            acc[0][0]+=a0*b0; acc[0][1]+=a0*b1; acc[0][2]+=a0*b2;
            acc[1][0]+=a1*b0; acc[1][1]+=a1*b1; acc[1][2]+=a1*b2;
            if(tid<96) accb += sbe[k0+kk]*sWl[kk][tid];
        }
    }
    #pragma unroll
    for(int e=0;e<2;e++){
        int p = pp + e*8;
        int base = (n*16+p)*96;
        g_Wfold[base+ts]    = acc[e][0];
        g_Wfold[base+ts+32] = acc[e][1];
        g_Wfold[base+ts+64] = acc[e][2];
    }
    if(tid<96) atomicAdd(&g_biasL[tid], accb);
}

// ---- fold2: Mpatch + bias2 ----
__global__ __launch_bounds__(256) void k_fold2n(const float* __restrict__ We,
        const float* __restrict__ be, const float* __restrict__ Wd,
        const float* __restrict__ bdres, const float* __restrict__ wdc,
        const float* __restrict__ bdc){
    __shared__ float sWe[16*257];
    __shared__ float sWd[16*257];
    __shared__ float swdc[16];
    int n = blockIdx.x, tid = threadIdx.x;
    for(int i2=tid;i2<4096;i2+=256){
        int r=i2>>8, c2=i2&255;
        sWe[r*257+c2]=We[i2];
        int j=i2>>4, q=i2&15;
        sWd[q*257+j]=Wd[i2];
    }
    if(tid<16) swdc[tid]=wdc[n*16+tid];
    __syncthreads();
    int i=tid&15, q=tid>>4;
    float s=0.f;
    #pragma unroll
    for(int p=0;p<16;p++) s += sWe[i*257+q*16+p]*swdc[p];
    for(int j=0;j<256;j++) s += sWe[i*257+j]*sWd[q*257+j];
    g_Mpatch[n*256+q*16+i]=s;
    if(tid<16){
        int qq=tid;
        float b=bdc[n]+bdres[qq];
        #pragma unroll
        for(int p=0;p<16;p++) b += be[qq*16+p]*swdc[p];
        for(int j=0;j<256;j++) b += be[j]*sWd[qq*257+j];
        g_bias2[n*16+qq]=b;
    }
}

// ---- transpose + symmetric split ----
__global__ __launch_bounds__(256) void k_transpose(const float* __restrict__ x){
    __shared__ float sa[128*21], sb[128*21];
    int b = blockIdx.x, c = blockIdx.y, tid = threadIdx.x;
    int l0 = c*128, l1 = (3-c)*128;
    const float* xb = x + (size_t)b*512*21;
    for(int i=tid;i<128*21;i+=256){ sa[i]=xb[l0*21+i]; sb[i]=xb[l1*21+i]; }
    __syncthreads();
    int t = tid&127;
    for(int d=(tid>>7); d<21; d+=2){
        size_t row = (size_t)(b*21+d);
        float va = sa[t*21+d], vb = sb[(127-t)*21+d], vb2 = sb[t*21+d];
        g_xt[row*512+l0+t]=va;
        g_xt[row*512+l1+t]=vb2;
        g_xs[row*256+l0+t]=va+vb;
        g_xd[row*256+l0+t]=va-vb;
    }
}

// ---- DCT GEMM: M64 x N128, K=256 ----
__global__ __launch_bounds__(256,3) void k_gemmA(
    const float* __restrict__ A0, const float* __restrict__ A1, int lda,
    const float* __restrict__ B0, const float* __restrict__ B1,
    float* __restrict__ C0, float* __restrict__ C1, int ldc)
{
    const float* A  = blockIdx.z ? A1 : A0;
    const float* Bm = blockIdx.z ? B1 : B0;
    float* C        = blockIdx.z ? C1 : C0;
    __shared__ float As[16][66];
    __shared__ __align__(16) float Bs[16][128];
    int row0 = blockIdx.x*64, col0 = blockIdx.y*128;
    int tid = threadIdx.x, tx = tid&31, ty = tid>>5;
    int am = tid&63, ak = (tid>>6)*4;
    int bn = (tid&31)*4, bk = tid>>5;
    ULL acc[4][4] = {};
    for(int kc=0;kc<256;kc+=16){
        float4 a4 = *(const float4*)&A[(size_t)(row0+am)*lda + kc + ak];
        As[ak+0][am]=a4.x; As[ak+1][am]=a4.y; As[ak+2][am]=a4.z; As[ak+3][am]=a4.w;
        float4 b0 = *(const float4*)&Bm[(size_t)(kc+bk)*256 + col0 + bn];
        float4 b1 = *(const float4*)&Bm[(size_t)(kc+bk+8)*256 + col0 + bn];
        *(float4*)&Bs[bk][bn]   = b0;
        *(float4*)&Bs[bk+8][bn] = b1;
        __syncthreads();
        #pragma unroll
        for(int k=0;k<16;k++){
            ULL av[4];
            #pragma unroll
            for(int rp=0;rp<4;rp++) av[rp] = *(const ULL*)&As[k][ty*8+2*rp];
            float4 bx = *(const float4*)&Bs[k][tx*4];
            ULL bd0=dup2(bx.x), bd1=dup2(bx.y), bd2=dup2(bx.z), bd3=dup2(bx.w);
            #pragma unroll
            for(int rp=0;rp<4;rp++){
                FFMA2(acc[rp][0],av[rp],bd0);
                FFMA2(acc[rp][1],av[rp],bd1);
                FFMA2(acc[rp][2],av[rp],bd2);
                FFMA2(acc[rp][3],av[rp],bd3);
            }
        }
        __syncthreads();
    }
    int col = col0 + tx*4;
    #pragma unroll
    for(int rp=0;rp<4;rp++){
        int r = row0 + ty*8 + 2*rp;
        F2U t0,t1,t2,t3; t0.u=acc[rp][0]; t1.u=acc[rp][1]; t2.u=acc[rp][2]; t3.u=acc[rp][3];
        float4 lo = make_float4(t0.f.x,t1.f.x,t2.f.x,t3.f.x);
        float4 hi = make_float4(t0.f.y,t1.f.y,t2.f.y,t3.f.y);
        *(float4*)&C[(size_t)r*ldc + col]     = lo;
        *(float4*)&C[(size_t)(r+1)*ldc + col] = hi;
    }
}

// ---- Output GEMM: M32 x N96(padded 128) ----
struct Cfg { const float* A; const float* B; float* C; const float* bias;
             int lda; int K; int epi; int az; };

__global__ __launch_bounds__(256,4) void k_gemmB(Cfg c0,
        const float* __restrict__ addp, float* __restrict__ outp)
{
    Cfg c = c0;
    __shared__ float As[16][34];
    __shared__ __align__(16) float Bs[16][128];
    int row0 = blockIdx.x*32;
    int tid = threadIdx.x, tx = tid&31, ty = tid>>5;
    int am = tid&31, ak = (tid>>5)*2;
    int bn = (tid&31)*4, bk = tid>>5;
    ULL acc[2][4] = {};
    float w = 0.f;
    if(c.az) w = g_att1[row0+am];
    for(int kc=0;kc<c.K;kc+=16){
        float2 a2;
        if(c.az){
            size_t o = (size_t)(row0+am)*512 + kc + ak;
            float2 z1v = *(const float2*)&g_z1[o];
            float2 z2v = *(const float2*)&g_z2[o];
            a2.x = z1v.x*w + z2v.x*(1.0f-w);
            a2.y = z1v.y*w + z2v.y*(1.0f-w);
        } else {
            a2 = *(const float2*)&c.A[(size_t)(row0+am)*c.lda + kc + ak];
        }
        As[ak][am]=a2.x; As[ak+1][am]=a2.y;
        float4 b0 = make_float4(0.f,0.f,0.f,0.f), b1 = b0;
        if(bn<96){
            b0 = *(const float4*)&c.B[(size_t)(kc+bk)*96 + bn];
            b1 = *(const float4*)&c.B[(size_t)(kc+bk+8)*96 + bn];
        }
        *(float4*)&Bs[bk][bn]   = b0;
        *(float4*)&Bs[bk+8][bn] = b1;
        __syncthreads();
        #pragma unroll
        for(int k=0;k<16;k++){
            ULL av0 = *(const ULL*)&As[k][ty*4];
            ULL av1 = *(const ULL*)&As[k][ty*4+2];
            float4 bx = *(const float4*)&Bs[k][tx*4];
            ULL bd0=dup2(bx.x), bd1=dup2(bx.y), bd2=dup2(bx.z), bd3=dup2(bx.w);
            FFMA2(acc[0][0],av0,bd0); FFMA2(acc[0][1],av0,bd1);
            FFMA2(acc[0][2],av0,bd2); FFMA2(acc[0][3],av0,bd3);
            FFMA2(acc[1][0],av1,bd0); FFMA2(acc[1][1],av1,bd1);
            FFMA2(acc[1][2],av1,bd2); FFMA2(acc[1][3],av1,bd3);
        }
        __syncthreads();
    }
    int col = tx*4;
    if(col<96){
        #pragma unroll
        for(int rp=0;rp<2;rp++){
            int r = row0 + ty*4 + 2*rp;
            F2U t0,t1,t2,t3; t0.u=acc[rp][0]; t1.u=acc[rp][1]; t2.u=acc[rp][2]; t3.u=acc[rp][3];
            float vlo[4]={t0.f.x,t1.f.x,t2.f.x,t3.f.x};
            float vhi[4]={t0.f.y,t1.f.y,t2.f.y,t3.f.y};
            #pragma unroll
            for(int e=0;e<2;e++){
                int row = r+e;
                #pragma unroll
                for(int j=0;j<4;j++){
                    float v = (e? vhi[j] : vlo[j]) + c.bias[col+j];
                    if(c.epi==3) v = gelu_f(v);
                    if(c.epi==4){
                        v += addp[(size_t)row*96+col+j];
                        int b = row/21, d = row - b*21;
                        outp[(size_t)b*2016 + (col+j)*21 + d] = v;
                    } else {
                        c.C[(size_t)row*96+col+j] = v;
                    }
                }
            }
        }
    }
}

// ---- energy (warp per row) ----
__global__ void k_energy(){
    int gw = (blockIdx.x*256+threadIdx.x)>>5, lane = threadIdx.x&31;
    const float* z = g_zsplit + (size_t)gw*512;
    float s=0.f;
    for(int i=lane;i<512;i+=32){ float x=z[i]; s+=x*x; }
    for(int o=16;o;o>>=1) s += __shfl_xor_sync(~0u,s,o);
    if(lane==0) g_energy[gw]=s;
}

// ---- fused median + global quantile radix select (parallel bucket scan); 2 blocks ----
__global__ __launch_bounds__(1024) void k_medquant(const float* __restrict__ thr_p){
    __shared__ float e[5376]; __shared__ float med[256];
    __shared__ unsigned vals[5376];
    __shared__ unsigned hist[256];
    __shared__ unsigned s_pref; __shared__ int s_r;
    int tid = threadIdx.x;
    for(int i=tid;i<5376;i+=1024) e[i]=g_energy[i];
    __syncthreads();
    if(tid<256){
        int b0 = tid*21;
        float m=0.f;
        for(int j=0;j<21;j++){
            float xj=e[b0+j]; int less=0,eq=0;
            for(int k2=0;k2<21;k2++){ float y=e[b0+k2]; less+=(y<xj); eq+=(y==xj); }
            if(less<=10 && 10<less+eq) m=xj;
        }
        med[tid]=m;
    }
    __syncthreads();
    for(int i=tid;i<5376;i+=1024){
        float nm = e[i]/(med[i/21]+1e-6f);
        vals[i]=__float_as_uint(nm);
        if(blockIdx.x==0) g_norme[i]=nm;
    }
    float pos = thr_p[0]*5375.0f;
    int i0 = (int)floorf(pos);
    int r = blockIdx.x ? ((i0+1<5376)?i0+1:5375) : i0;
    unsigned prefix=0, msk=0;
    for(int shift=24;shift>=0;shift-=8){
        if(tid<256) hist[tid]=0;
        __syncthreads();
        for(int i=tid;i<5376;i+=1024){
            unsigned xv=vals[i];
            if((xv&msk)==prefix) atomicAdd(&hist[(xv>>shift)&255],1u);
        }
        __syncthreads();
        // parallel inclusive scan over 256 buckets
        #pragma unroll
        for(int o=1;o<256;o<<=1){
            unsigned y=0;
            if(tid<256 && tid>=(unsigned)o) y=hist[tid-o];
            __syncthreads();
            if(tid<256) hist[tid]+=y;
            __syncthreads();
        }
        if(tid<256){
            unsigned lo = tid? hist[tid-1]:0u, hi=hist[tid];
            if(lo<=(unsigned)r && (unsigned)r<hi){ s_pref=prefix|((unsigned)tid<<shift); s_r=r-(int)lo; }
        }
        __syncthreads();
        prefix=s_pref; r=s_r; msk|=(255u<<shift);
        __syncthreads();
    }
    if(tid==0) g_thr[blockIdx.x]=__uint_as_float(prefix);
}

// ---- mask + scale + gelu + CH stats ----
__global__ void k_maskgelu(const float* __restrict__ wdct, const float* __restrict__ bdct,
                           const float* __restrict__ thr_p){
    __shared__ float rs[2];
    int bd = blockIdx.x, tid = threadIdx.x;
    int d = bd - (bd/21)*21;
    float pos = thr_p[0]*5375.0f;
    float fr = pos - floorf(pos);
    float thr = g_thr[0] + fr*(g_thr[1]-g_thr[0]);
    float msk = (g_norme[bd] > thr) ? 1.f : 0.f;
    float wd = wdct[d]*msk, b0 = bdct[d];
    if(tid<2) rs[tid]=0.f;
    __syncthreads();
    float ls=0.f, lq=0.f;
    #pragma unroll
    for(int h=0;h<2;h++){
        size_t o=(size_t)bd*512 + tid + h*256;
        float g2 = gelu_f(g_zsplit[o]*wd + b0);
        g_zsplit[o]=g2; ls+=g2; lq+=g2*g2;
    }
    #pragma unroll
    for(int o=16;o;o>>=1){ ls += __shfl_xor_sync(~0u,ls,o); lq += __shfl_xor_sync(~0u,lq,o); }
    if((tid&31)==0){ atomicAdd(&rs[0],ls); atomicAdd(&rs[1],lq); }
    __syncthreads();
    if(tid==0){ atomicAdd(&g_stats[CHB+d],rs[0]); atomicAdd(&g_stats[CHB+32+d],rs[1]); }
}

// ---- patch branch: PN stats only ----
__global__ __launch_bounds__(256) void k_patch(){
    __shared__ float xr[512]; __shared__ float ps[32], pq[32];
    int bd = blockIdx.x, tid = threadIdx.x;
    size_t r5 = (size_t)bd*512;
    xr[tid]     = g_xt[r5+tid];
    xr[tid+256] = g_xt[r5+tid+256];
    if(tid<32){ ps[tid]=0.f; pq[tid]=0.f; }
    __syncthreads();
    #pragma unroll
    for(int h=0;h<2;h++){
        int c2 = tid + h*256, n = c2>>4, q = c2&15;
        float s = g_bias2[c2];
        const float* Mr = &g_Mpatch[n*256+q*16];
        const float* xp = &xr[n*16];
        #pragma unroll
        for(int i=0;i<16;i++) s += xp[i]*Mr[i];
        float sq = s*s;
        #pragma unroll
        for(int o=8;o;o>>=1){ s += __shfl_xor_sync(~0u,s,o); sq += __shfl_xor_sync(~0u,sq,o); }
        if((tid&15)==0){ atomicAdd(&ps[n],s); atomicAdd(&pq[n],sq); }
    }
    __syncthreads();
    if(tid<32){ atomicAdd(&g_stats[PNB+tid],ps[tid]); atomicAdd(&g_stats[PNB+32+tid],pq[tid]); }
}

// ---- recompute s1 from xt, z2 = gelu(bn(s1)); DN stats of conv3(z2) ----
__global__ void k_conv(const float* __restrict__ wdc1, const float* __restrict__ bdc1,
                       const float* __restrict__ gp, const float* __restrict__ bp){
    __shared__ float xr[512]; __shared__ float z2s[512];
    __shared__ float ss[32], sq2[32];
    __shared__ float pa[32], pc[32];
    int bd = blockIdx.x, tid = threadIdx.x;
    size_t r5 = (size_t)bd*512;
    xr[tid]     = g_xt[r5+tid];
    xr[tid+256] = g_xt[r5+tid+256];
    if(tid<32){
        ss[tid]=0.f; sq2[tid]=0.f;
        float s=g_stats[PNB+tid], sq=g_stats[PNB+32+tid];
        float m2=s*(1.0f/86016.0f), v2=sq*(1.0f/86016.0f)-m2*m2;
        float aa=gp[tid]*rsqrtf(v2+1e-5f);
        pa[tid]=aa; pc[tid]=bp[tid]-m2*aa;
    }
    __syncthreads();
    #pragma unroll
    for(int h=0;h<2;h++){
        int c = tid + h*256, n = c>>4, q = c&15;
        float s = g_bias2[c];
        const float* Mr = &g_Mpatch[n*256+q*16];
        const float* xp = &xr[n*16];
        #pragma unroll
        for(int i=0;i<16;i++) s += xp[i]*Mr[i];
        float g2 = gelu_f(s*pa[n] + pc[n]);
        z2s[c]=g2; g_z2[r5+c]=g2;
    }
    __syncthreads();
    #pragma unroll
    for(int h=0;h<2;h++){
        int c = tid + h*256, n = c>>4, q = c&15;
        float l = q>0 ? z2s[c-1] : 0.f;
        float m0 = z2s[c];
        float r = q<15 ? z2s[c+1] : 0.f;
        float zc = wdc1[n*3+0]*l + wdc1[n*3+1]*m0 + wdc1[n*3+2]*r + bdc1[n];
        float s=zc, sq=zc*zc;
        #pragma unroll
        for(int o=8;o;o>>=1){ s += __shfl_xor_sync(~0u,s,o); sq += __shfl_xor_sync(~0u,sq,o); }
        if((tid&15)==0){ atomicAdd(&ss[n],s); atomicAdd(&sq2[n],sq); }
    }
    __syncthreads();
    if(tid<32){ atomicAdd(&g_stats[DNB+tid],ss[tid]); atomicAdd(&g_stats[DNB+32+tid],sq2[tid]); }
}

// ---- fused: recombine (z1 from u/v + CH BN + residual) + conv3/z2f + attention dot ----
__global__ void k_rz2att(const float* __restrict__ wdct, const float* __restrict__ bdct,
                         const float* __restrict__ gd, const float* __restrict__ bD,
                         const float* __restrict__ wdc1, const float* __restrict__ bdc1,
                         const float* __restrict__ adwb,
                         const float* __restrict__ gdn, const float* __restrict__ bdn){
    __shared__ float z1s[512], z2s[512]; __shared__ float red[8];
    __shared__ float da[32], dc[32];
    int bd = blockIdx.x, tid = threadIdx.x;
    int d = bd - (bd/21)*21;
    size_t r5 = (size_t)bd*512;
    z2s[tid]     = g_z2[r5+tid];
    z2s[tid+256] = g_z2[r5+tid+256];
    if(tid<32){
        float s=g_stats[DNB+tid], sq=g_stats[DNB+32+tid];
        float m2=s*(1.0f/86016.0f), v2=sq*(1.0f/86016.0f)-m2*m2;
        float aa=gdn[tid]*rsqrtf(v2+1e-5f);
        da[tid]=aa; dc[tid]=bdn[tid]-m2*aa;
    }
    {
        float s = g_stats[CHB+d], sq = g_stats[CHB+32+d];
        float mm = s*(1.0f/131072.0f), vv = sq*(1.0f/131072.0f)-mm*mm;
        float a = gd[d]*rsqrtf(vv+1e-5f);
        float c = bD[d]-mm*a;
        float wd = wdct[d], b0 = bdct[d];
        int m = tid;
        size_t r2 = (size_t)bd*256+m;
        float u = g_u[r2], v = g_v[r2];
        float x0 = g_xt[r5+m], x1 = g_xt[r5+511-m];
        float zl = a*(u+v) + c*(g_ce[m]+g_co[m]) + x0*wd + b0;
        float zh = a*(u-v) + c*(g_ce[m]-g_co[m]) + x1*wd + b0;
        z1s[m]=zl; z1s[511-m]=zh;
        g_z1[r5+m]=zl; g_z1[r5+511-m]=zh;
    }
    __syncthreads();
    float dot = 0.f;
    #pragma unroll
    for(int h=0;h<2;h++){
        int c = tid + h*256, n = c>>4, q = c&15;
        float l = q>0 ? z2s[c-1] : 0.f;
        float m0 = z2s[c];
        float r = q<15 ? z2s[c+1] : 0.f;
        float zc = wdc1[n*3+0]*l + wdc1[n*3+1]*m0 + wdc1[n*3+2]*r + bdc1[n];
        float z2f = gelu_f(zc*da[n] + dc[n]) + m0;
        g_z2[r5+c] = z2f;
        dot += z1s[c]*z2f*g_attcoef[c];
    }
    #pragma unroll
    for(int o=16;o;o>>=1) dot += __shfl_xor_sync(~0u,dot,o);
    if((tid&31)==0) red[tid>>5]=dot;
    __syncthreads();
    if(tid<8){
        float s = red[tid];
        #pragma unroll
        for(int o=4;o;o>>=1) s += __shfl_xor_sync(0xffu,s,o);
        if(tid==0){
            float att = s + adwb[0];
            g_att[bd]=att;
            atomicAdd(&g_stats[ATT_SUM],att);
            atomicAdd(&g_stats[ATT_SQ],att*att);
        }
    }
}

// ---- BN(att) + gelu + softmax over 21 ----
__global__ void k_softmax(const float* __restrict__ ag, const float* __restrict__ ab,
                          const float* __restrict__ cw, const float* __restrict__ cb){
    int b = blockIdx.x, t = threadIdx.x;
    float inv = 1.0f/5376.0f;
    float m = g_stats[ATT_SUM]*inv;
    float v = g_stats[ATT_SQ]*inv - m*m;
    float val = -1e30f;
    if(t<21){
        float a = g_att[b*21+t];
        a = ag[0]*(a-m)*rsqrtf(v+1e-5f)+ab[0];
        a = gelu_f(a);
        val = a*cw[0]+cb[0];
    }
    float mx = val;
    for(int o=16;o;o>>=1) mx = fmaxf(mx,__shfl_xor_sync(~0u,mx,o));
    float e = (t<21) ? expf(val-mx) : 0.f;
    float sum = e;
    for(int o=16;o;o>>=1) sum += __shfl_xor_sync(~0u,sum,o);
    if(t<21) g_att1[b*21+t] = e/sum;
}

extern "C" void kernel_launch(void* const* d_in, const int* in_sizes, int n_in,
                              void* d_out, int out_size){
    const float* x        =(const float*)d_in[0];
    const float* w_dct    =(const float*)d_in[1];
    const float* b_dct    =(const float*)d_in[2];
    const float* W_embed  =(const float*)d_in[3];
    const float* b_embed  =(const float*)d_in[4];
    const float* W_linres =(const float*)d_in[5];
    const float* b_linres =(const float*)d_in[6];
    const float* W_dres   =(const float*)d_in[7];
    const float* b_dres   =(const float*)d_in[8];
    const float* w_dc     =(const float*)d_in[9];
    const float* b_dc     =(const float*)d_in[10];
    const float* w_dc1    =(const float*)d_in[11];
    const float* b_dc1    =(const float*)d_in[12];
    const float* g_dctn   =(const float*)d_in[13];
    const float* b_dctn   =(const float*)d_in[14];
    const float* g_patn   =(const float*)d_in[15];
    const float* b_patn   =(const float*)d_in[16];
    const float* g_depn   =(const float*)d_in[17];
    const float* b_depn   =(const float*)d_in[18];
    const float* thr_p    =(const float*)d_in[19];
    const float* W_m1     =(const float*)d_in[20];
    const float* b_m1     =(const float*)d_in[21];
    const float* W_m2     =(const float*)d_in[22];
    const float* b_m2     =(const float*)d_in[23];
    const float* a_dw_w   =(const float*)d_in[24];
    const float* a_dw_b   =(const float*)d_in[25];
    const float* a_cw     =(const float*)d_in[26];
    const float* a_cb     =(const float*)d_in[27];
    const float* a_g      =(const float*)d_in[28];
    const float* a_b      =(const float*)d_in[29];
    float* out = (float*)d_out;

    float *p_xs,*p_xd,*p_BE,*p_BO,*p_BPe,*p_BPo,*p_zs,*p_u,*p_v,*p_xt,*p_Wf,*p_bL,*p_zr,*p_h;
    cudaGetSymbolAddress((void**)&p_xs,  g_xs);
    cudaGetSymbolAddress((void**)&p_xd,  g_xd);
    cudaGetSymbolAddress((void**)&p_BE,  g_BE);
    cudaGetSymbolAddress((void**)&p_BO,  g_BO);
    cudaGetSymbolAddress((void**)&p_BPe, g_BPe);
    cudaGetSymbolAddress((void**)&p_BPo, g_BPo);
    cudaGetSymbolAddress((void**)&p_zs,  g_zsplit);
    cudaGetSymbolAddress((void**)&p_u,   g_u);
    cudaGetSymbolAddress((void**)&p_v,   g_v);
    cudaGetSymbolAddress((void**)&p_xt,  g_xt);
    cudaGetSymbolAddress((void**)&p_Wf,  g_Wfold);
    cudaGetSymbolAddress((void**)&p_bL,  g_biasL);
    cudaGetSymbolAddress((void**)&p_zr,  g_zres);
    cudaGetSymbolAddress((void**)&p_h,   g_h);

    cudaStream_t s2;
    cudaStreamCreateWithFlags(&s2, cudaStreamNonBlocking);
    cudaEvent_t evA, evM, evT, evJ;
    cudaEventCreateWithFlags(&evA, cudaEventDisableTiming);
    cudaEventCreateWithFlags(&evM, cudaEventDisableTiming);
    cudaEventCreateWithFlags(&evT, cudaEventDisableTiming);
    cudaEventCreateWithFlags(&evJ, cudaEventDisableTiming);

    // Fork s2 into the capture FIRST via an event on the capturing stream.
    cudaEventRecord(evA, 0);
    cudaStreamWaitEvent(s2, evA, 0);

    // side stream: mats + folds
    k_mats<<<257,256,0,s2>>>(a_dw_w, b_linres);
    cudaEventRecord(evM, s2);
    k_fold1n<<<32,256,0,s2>>>(W_embed, W_linres, b_embed);
    k_fold2n<<<32,256,0,s2>>>(W_embed, b_embed, W_dres, b_dres, w_dc, b_dc);

    // main stream: transpose
    k_transpose<<<dim3(256,2),256>>>(x);
    cudaEventRecord(evT, 0);

    // side continues after transpose: patch branch + zres GEMM
    cudaStreamWaitEvent(s2, evT, 0);
    k_patch<<<BD,256,0,s2>>>();
    k_conv<<<BD,256,0,s2>>>(w_dc1,b_dc1,g_patn,b_patn);
    Cfg cW; cW.A=p_xt; cW.B=p_Wf; cW.C=p_zr; cW.bias=p_bL; cW.lda=512; cW.K=512; cW.epi=2; cW.az=0;
    k_gemmB<<<dim3(168,1,1),256,0,s2>>>(cW,nullptr,nullptr);
    cudaEventRecord(evJ, s2);

    // main: DCT chain
    cudaStreamWaitEvent(0, evM, 0);
    k_gemmA<<<dim3(84,2,2),256>>>(p_xs,p_xd,256, p_BE,p_BO, p_zs,p_zs+256,512);
    k_energy<<<672,256>>>();
    k_medquant<<<2,1024>>>(thr_p);
    k_maskgelu<<<BD,256>>>(w_dct,b_dct,thr_p);
    k_gemmA<<<dim3(84,2,2),256>>>(p_zs,p_zs+256,512, p_BPe,p_BPo, p_u,p_v,256);

    // join: fused recombine + z2f + attention
    cudaStreamWaitEvent(0, evJ, 0);
    k_rz2att<<<BD,256>>>(w_dct,b_dct,g_dctn,b_dctn,w_dc1,b_dc1,a_dw_b,g_depn,b_depn);
    k_softmax<<<256,32>>>(a_g,a_b,a_cw,a_cb);
    Cfg cM1; cM1.A=nullptr; cM1.B=W_m1; cM1.C=p_h; cM1.bias=b_m1; cM1.lda=512; cM1.K=512; cM1.epi=3; cM1.az=1;
    k_gemmB<<<dim3(168,1,1),256>>>(cM1,nullptr,nullptr);
    Cfg cM2; cM2.A=p_h; cM2.B=W_m2; cM2.C=nullptr; cM2.bias=b_m2; cM2.lda=96; cM2.K=96; cM2.epi=4; cM2.az=0;
    k_gemmB<<<dim3(168,1,1),256>>>(cM2,p_zr,out);
}

// round 10
// speedup vs baseline: 1.7538x; 1.7538x over previous
#include <cuda_runtime.h>
#include <cuda_bf16.h>

#define BD 5376
#define CHB 0
#define PNB 128
#define DNB 256
#define ATT_SUM 384
#define ATT_SQ 385
#define PIF 3.14159265358979323846f

typedef unsigned long long ULL;
union F2U { ULL u; float2 f; };

__device__ float g_BE[65536], g_BO[65536], g_BPe[65536], g_BPo[65536];
__device__ float g_ce[256], g_co[256], g_attcoef[512];
__device__ float g_Wfold[49152], g_biasL[96], g_Mpatch[8192], g_bias2[512];
__device__ float g_xt[BD*512], g_xs[BD*256], g_xd[BD*256];
__device__ float g_zsplit[BD*512], g_u[BD*256], g_v[BD*256], g_z1[BD*512];
__device__ float g_s1[BD*512], g_z2[BD*512];
__device__ float g_zres[BD*96], g_h[BD*96];
__device__ float g_energy[BD], g_norme[BD], g_att[BD], g_att1[BD];
__device__ float g_thr[2], g_stats[512];

__device__ __forceinline__ float gelu_f(float x){
    return 0.5f*x*(1.0f+erff(x*0.70710678118654752440f));
}
__device__ __forceinline__ ULL dup2(float x){ ULL r; asm("mov.b64 %0,{%1,%1};":"=l"(r):"f"(x)); return r; }
#define FFMA2(d,a,b) asm("fma.rn.f32x2 %0, %1, %2, %0;" : "+l"(d) : "l"(a), "l"(b))

// ---- DCT matrices + attcoef + stats zero + biasL init ----
__global__ void k_mats(const float* __restrict__ adw, const float* __restrict__ bl){
    int bm = blockIdx.x, t = threadIdx.x;
    if(bm < 256){
        int m = bm, j = t;
        float am = PIF*(float)(2*m+1);
        float ce = cosf(am*(float)(2*j)*(1.0f/1024.0f));
        float co = cosf(am*(float)(2*j+1)*(1.0f/1024.0f));
        g_BE[m*256+j] = 2.0f*ce;
        g_BO[m*256+j] = 2.0f*co;
        float bpe = ce*((j==0)?0.5f:1.0f)*(1.0f/512.0f);
        float bpo = co*(1.0f/512.0f);
        g_BPe[j*256+m] = bpe;
        g_BPo[j*256+m] = bpo;
        __shared__ float r1[256], r2[256];
        r1[t]=bpe; r2[t]=bpo; __syncthreads();
        for(int o=128;o>0;o>>=1){ if(t<o){ r1[t]+=r1[t+o]; r2[t]+=r2[t+o]; } __syncthreads(); }
        if(t==0){ g_ce[m]=r1[0]; g_co[m]=r2[0]; }
    } else {
        float rL = sqrtf(512.0f);
        for(int m=t; m<512; m+=256){
            float am = PIF*(float)(2*m+1);
            float s = 0.f;
            for(int k=0;k<5;k++){
                float c = 2.0f*cosf(am*(float)k*(1.0f/1024.0f));
                float so = (k==0)? (0.5f/rL) : (0.5f*sqrtf(2.0f)/rL);
                s += adw[k]*so*c;
            }
            g_attcoef[m]=s;
        }
        g_stats[t]=0.f; g_stats[t+256]=0.f;
        if(t<96) g_biasL[t]=bl[t];
    }
}

// ---- fold1: Wfold + biasL ----
__global__ __launch_bounds__(256) void k_fold1n(const float* __restrict__ We,
        const float* __restrict__ Wl, const float* __restrict__ be){
    __shared__ float sWe[4096];
    __shared__ float sbe[256];
    __shared__ float sWl[32][100];
    int n = blockIdx.x, tid = threadIdx.x;
    for(int i=tid;i<4096;i+=256) sWe[i]=We[i];
    sbe[tid]=be[tid];
    int pp = tid>>5, ts = tid&31;
    float acc[2][3] = {};
    float accb = 0.f;
    for(int k0=0;k0<256;k0+=32){
        __syncthreads();
        for(int i2=tid;i2<32*96;i2+=256){
            int r=i2/96, c2=i2-r*96;
            sWl[r][c2]=Wl[(size_t)(n*256+k0+r)*96+c2];
        }
        __syncthreads();
        #pragma unroll
        for(int kk=0;kk<32;kk++){
            float a0=sWe[pp*256+k0+kk], a1=sWe[(pp+8)*256+k0+kk];
            float b0=sWl[kk][ts], b1=sWl[kk][ts+32], b2=sWl[kk][ts+64];
            acc[0][0]+=a0*b0; acc[0][1]+=a0*b1; acc[0][2]+=a0*b2;
            acc[1][0]+=a1*b0; acc[1][1]+=a1*b1; acc[1][2]+=a1*b2;
            if(tid<96) accb += sbe[k0+kk]*sWl[kk][tid];
        }
    }
    #pragma unroll
    for(int e=0;e<2;e++){
        int p = pp + e*8;
        int base = (n*16+p)*96;
        g_Wfold[base+ts]    = acc[e][0];
        g_Wfold[base+ts+32] = acc[e][1];
        g_Wfold[base+ts+64] = acc[e][2];
    }
    if(tid<96) atomicAdd(&g_biasL[tid], accb);
}

// ---- fold2: Mpatch + bias2 ----
__global__ __launch_bounds__(256) void k_fold2n(const float* __restrict__ We,
        const float* __restrict__ be, const float* __restrict__ Wd,
        const float* __restrict__ bdres, const float* __restrict__ wdc,
        const float* __restrict__ bdc){
    __shared__ float sWe[16*257];
    __shared__ float sWd[16*257];
    __shared__ float swdc[16];
    int n = blockIdx.x, tid = threadIdx.x;
    for(int i2=tid;i2<4096;i2+=256){
        int r=i2>>8, c2=i2&255;
        sWe[r*257+c2]=We[i2];
        int j=i2>>4, q=i2&15;
        sWd[q*257+j]=Wd[i2];
    }
    if(tid<16) swdc[tid]=wdc[n*16+tid];
    __syncthreads();
    int i=tid&15, q=tid>>4;
    float s=0.f;
    #pragma unroll
    for(int p=0;p<16;p++) s += sWe[i*257+q*16+p]*swdc[p];
    for(int j=0;j<256;j++) s += sWe[i*257+j]*sWd[q*257+j];
    g_Mpatch[n*256+q*16+i]=s;
    if(tid<16){
        int qq=tid;
        float b=bdc[n]+bdres[qq];
        #pragma unroll
        for(int p=0;p<16;p++) b += be[qq*16+p]*swdc[p];
        for(int j=0;j<256;j++) b += be[j]*sWd[qq*257+j];
        g_bias2[n*16+qq]=b;
    }
}

// ---- transpose + symmetric split ----
__global__ __launch_bounds__(256) void k_transpose(const float* __restrict__ x){
    __shared__ float sa[128*21], sb[128*21];
    int b = blockIdx.x, c = blockIdx.y, tid = threadIdx.x;
    int l0 = c*128, l1 = (3-c)*128;
    const float* xb = x + (size_t)b*512*21;
    for(int i=tid;i<128*21;i+=256){ sa[i]=xb[l0*21+i]; sb[i]=xb[l1*21+i]; }
    __syncthreads();
    int t = tid&127;
    for(int d=(tid>>7); d<21; d+=2){
        size_t row = (size_t)(b*21+d);
        float va = sa[t*21+d], vb = sb[(127-t)*21+d], vb2 = sb[t*21+d];
        g_xt[row*512+l0+t]=va;
        g_xt[row*512+l1+t]=vb2;
        g_xs[row*256+l0+t]=va+vb;
        g_xd[row*256+l0+t]=va-vb;
    }
}

// ---- DCT GEMM: M64 x N128, K=256 ----
__global__ __launch_bounds__(256,3) void k_gemmA(
    const float* __restrict__ A0, const float* __restrict__ A1, int lda,
    const float* __restrict__ B0, const float* __restrict__ B1,
    float* __restrict__ C0, float* __restrict__ C1, int ldc)
{
    const float* A  = blockIdx.z ? A1 : A0;
    const float* Bm = blockIdx.z ? B1 : B0;
    float* C        = blockIdx.z ? C1 : C0;
    __shared__ float As[16][66];
    __shared__ __align__(16) float Bs[16][128];
    int row0 = blockIdx.x*64, col0 = blockIdx.y*128;
    int tid = threadIdx.x, tx = tid&31, ty = tid>>5;
    int am = tid&63, ak = (tid>>6)*4;
    int bn = (tid&31)*4, bk = tid>>5;
    ULL acc[4][4] = {};
    for(int kc=0;kc<256;kc+=16){
        float4 a4 = *(const float4*)&A[(size_t)(row0+am)*lda + kc + ak];
        As[ak+0][am]=a4.x; As[ak+1][am]=a4.y; As[ak+2][am]=a4.z; As[ak+3][am]=a4.w;
        float4 b0 = *(const float4*)&Bm[(size_t)(kc+bk)*256 + col0 + bn];
        float4 b1 = *(const float4*)&Bm[(size_t)(kc+bk+8)*256 + col0 + bn];
        *(float4*)&Bs[bk][bn]   = b0;
        *(float4*)&Bs[bk+8][bn] = b1;
        __syncthreads();
        #pragma unroll
        for(int k=0;k<16;k++){
            ULL av[4];
            #pragma unroll
            for(int rp=0;rp<4;rp++) av[rp] = *(const ULL*)&As[k][ty*8+2*rp];
            float4 bx = *(const float4*)&Bs[k][tx*4];
            ULL bd0=dup2(bx.x), bd1=dup2(bx.y), bd2=dup2(bx.z), bd3=dup2(bx.w);
            #pragma unroll
            for(int rp=0;rp<4;rp++){
                FFMA2(acc[rp][0],av[rp],bd0);
                FFMA2(acc[rp][1],av[rp],bd1);
                FFMA2(acc[rp][2],av[rp],bd2);
                FFMA2(acc[rp][3],av[rp],bd3);
            }
        }
        __syncthreads();
    }
    int col = col0 + tx*4;
    #pragma unroll
    for(int rp=0;rp<4;rp++){
        int r = row0 + ty*8 + 2*rp;
        F2U t0,t1,t2,t3; t0.u=acc[rp][0]; t1.u=acc[rp][1]; t2.u=acc[rp][2]; t3.u=acc[rp][3];
        float4 lo = make_float4(t0.f.x,t1.f.x,t2.f.x,t3.f.x);
        float4 hi = make_float4(t0.f.y,t1.f.y,t2.f.y,t3.f.y);
        *(float4*)&C[(size_t)r*ldc + col]     = lo;
        *(float4*)&C[(size_t)(r+1)*ldc + col] = hi;
    }
}

// ---- Output GEMM: M32 x N96(padded 128) ----
struct Cfg { const float* A; const float* B; float* C; const float* bias;
             int lda; int K; int epi; int az; };

__global__ __launch_bounds__(256,4) void k_gemmB(Cfg c0,
        const float* __restrict__ addp, float* __restrict__ outp)
{
    Cfg c = c0;
    __shared__ float As[16][34];
    __shared__ __align__(16) float Bs[16][128];
    int row0 = blockIdx.x*32;
    int tid = threadIdx.x, tx = tid&31, ty = tid>>5;
    int am = tid&31, ak = (tid>>5)*2;
    int bn = (tid&31)*4, bk = tid>>5;
    ULL acc[2][4] = {};
    float w = 0.f;
    if(c.az) w = g_att1[row0+am];
    for(int kc=0;kc<c.K;kc+=16){
        float2 a2;
        if(c.az){
            size_t o = (size_t)(row0+am)*512 + kc + ak;
            float2 z1v = *(const float2*)&g_z1[o];
            float2 z2v = *(const float2*)&g_z2[o];
            a2.x = z1v.x*w + z2v.x*(1.0f-w);
            a2.y = z1v.y*w + z2v.y*(1.0f-w);
        } else {
            a2 = *(const float2*)&c.A[(size_t)(row0+am)*c.lda + kc + ak];
        }
        As[ak][am]=a2.x; As[ak+1][am]=a2.y;
        float4 b0 = make_float4(0.f,0.f,0.f,0.f), b1 = b0;
        if(bn<96){
            b0 = *(const float4*)&c.B[(size_t)(kc+bk)*96 + bn];
            b1 = *(const float4*)&c.B[(size_t)(kc+bk+8)*96 + bn];
        }
        *(float4*)&Bs[bk][bn]   = b0;
        *(float4*)&Bs[bk+8][bn] = b1;
        __syncthreads();
        #pragma unroll
        for(int k=0;k<16;k++){
            ULL av0 = *(const ULL*)&As[k][ty*4];
            ULL av1 = *(const ULL*)&As[k][ty*4+2];
            float4 bx = *(const float4*)&Bs[k][tx*4];
            ULL bd0=dup2(bx.x), bd1=dup2(bx.y), bd2=dup2(bx.z), bd3=dup2(bx.w);
            FFMA2(acc[0][0],av0,bd0); FFMA2(acc[0][1],av0,bd1);
            FFMA2(acc[0][2],av0,bd2); FFMA2(acc[0][3],av0,bd3);
            FFMA2(acc[1][0],av1,bd0); FFMA2(acc[1][1],av1,bd1);
            FFMA2(acc[1][2],av1,bd2); FFMA2(acc[1][3],av1,bd3);
        }
        __syncthreads();
    }
    int col = tx*4;
    if(col<96){
        #pragma unroll
        for(int rp=0;rp<2;rp++){
            int r = row0 + ty*4 + 2*rp;
            F2U t0,t1,t2,t3; t0.u=acc[rp][0]; t1.u=acc[rp][1]; t2.u=acc[rp][2]; t3.u=acc[rp][3];
            float vlo[4]={t0.f.x,t1.f.x,t2.f.x,t3.f.x};
            float vhi[4]={t0.f.y,t1.f.y,t2.f.y,t3.f.y};
            #pragma unroll
            for(int e=0;e<2;e++){
                int row = r+e;
                #pragma unroll
                for(int j=0;j<4;j++){
                    float v = (e? vhi[j] : vlo[j]) + c.bias[col+j];
                    if(c.epi==3) v = gelu_f(v);
                    if(c.epi==4){
                        v += addp[(size_t)row*96+col+j];
                        int b = row/21, d = row - b*21;
                        outp[(size_t)b*2016 + (col+j)*21 + d] = v;
                    } else {
                        c.C[(size_t)row*96+col+j] = v;
                    }
                }
            }
        }
    }
}

// ---- energy (warp per row) ----
__global__ void k_energy(){
    int gw = (blockIdx.x*256+threadIdx.x)>>5, lane = threadIdx.x&31;
    const float* z = g_zsplit + (size_t)gw*512;
    float s=0.f;
    for(int i=lane;i<512;i+=32){ float x=z[i]; s+=x*x; }
    for(int o=16;o;o>>=1) s += __shfl_xor_sync(~0u,s,o);
    if(lane==0) g_energy[gw]=s;
}

// ---- fused median + global quantile radix select (parallel bucket scan); 2 blocks ----
__global__ __launch_bounds__(1024) void k_medquant(const float* __restrict__ thr_p){
    __shared__ float e[5376]; __shared__ float med[256];
    __shared__ unsigned vals[5376];
    __shared__ unsigned hist[256];
    __shared__ unsigned s_pref; __shared__ int s_r;
    int tid = threadIdx.x;
    for(int i=tid;i<5376;i+=1024) e[i]=g_energy[i];
    __syncthreads();
    if(tid<256){
        int b0 = tid*21;
        float m=0.f;
        for(int j=0;j<21;j++){
            float xj=e[b0+j]; int less=0,eq=0;
            for(int k2=0;k2<21;k2++){ float y=e[b0+k2]; less+=(y<xj); eq+=(y==xj); }
            if(less<=10 && 10<less+eq) m=xj;
        }
        med[tid]=m;
    }
    __syncthreads();
    for(int i=tid;i<5376;i+=1024){
        float nm = e[i]/(med[i/21]+1e-6f);
        vals[i]=__float_as_uint(nm);
        if(blockIdx.x==0) g_norme[i]=nm;
    }
    float pos = thr_p[0]*5375.0f;
    int i0 = (int)floorf(pos);
    int r = blockIdx.x ? ((i0+1<5376)?i0+1:5375) : i0;
    unsigned prefix=0, msk=0;
    for(int shift=24;shift>=0;shift-=8){
        if(tid<256) hist[tid]=0;
        __syncthreads();
        for(int i=tid;i<5376;i+=1024){
            unsigned xv=vals[i];
            if((xv&msk)==prefix) atomicAdd(&hist[(xv>>shift)&255],1u);
        }
        __syncthreads();
        // parallel inclusive scan over 256 buckets
        for(int o=1;o<256;o<<=1){
            unsigned y=0;
            if(tid<256 && tid>=(unsigned)o) y=hist[tid-o];
            __syncthreads();
            if(tid<256) hist[tid]+=y;
            __syncthreads();
        }
        if(tid<256){
            unsigned lo = tid? hist[tid-1]:0u, hi=hist[tid];
            if(lo<=(unsigned)r && (unsigned)r<hi){ s_pref=prefix|((unsigned)tid<<shift); s_r=r-(int)lo; }
        }
        __syncthreads();
        prefix=s_pref; r=s_r; msk|=(255u<<shift);
        __syncthreads();
    }
    if(tid==0) g_thr[blockIdx.x]=__uint_as_float(prefix);
}

// ---- mask + scale + gelu + CH stats ----
__global__ void k_maskgelu(const float* __restrict__ wdct, const float* __restrict__ bdct,
                           const float* __restrict__ thr_p){
    __shared__ float rs[2];
    int bd = blockIdx.x, tid = threadIdx.x;
    int d = bd - (bd/21)*21;
    float pos = thr_p[0]*5375.0f;
    float fr = pos - floorf(pos);
    float thr = g_thr[0] + fr*(g_thr[1]-g_thr[0]);
    float msk = (g_norme[bd] > thr) ? 1.f : 0.f;
    float wd = wdct[d]*msk, b0 = bdct[d];
    if(tid<2) rs[tid]=0.f;
    __syncthreads();
    float ls=0.f, lq=0.f;
    #pragma unroll
    for(int h=0;h<2;h++){
        size_t o=(size_t)bd*512 + tid + h*256;
        float g2 = gelu_f(g_zsplit[o]*wd + b0);
        g_zsplit[o]=g2; ls+=g2; lq+=g2*g2;
    }
    #pragma unroll
    for(int o=16;o;o>>=1){ ls += __shfl_xor_sync(~0u,ls,o); lq += __shfl_xor_sync(~0u,lq,o); }
    if((tid&31)==0){ atomicAdd(&rs[0],ls); atomicAdd(&rs[1],lq); }
    __syncthreads();
    if(tid==0){ atomicAdd(&g_stats[CHB+d],rs[0]); atomicAdd(&g_stats[CHB+32+d],rs[1]); }
}

// ---- recombine inverse-DCT + inline CH BN + residual ----
__global__ __launch_bounds__(256) void k_recombine(const float* __restrict__ wdct,
        const float* __restrict__ bdct, const float* __restrict__ gd,
        const float* __restrict__ bD){
    int bd = blockIdx.x, m = threadIdx.x;
    int d = bd - (bd/21)*21;
    float s = g_stats[CHB+d], sq = g_stats[CHB+32+d];
    float mm = s*(1.0f/131072.0f), vv = sq*(1.0f/131072.0f)-mm*mm;
    float a = gd[d]*rsqrtf(vv+1e-5f);
    float c = bD[d]-mm*a;
    float wd = wdct[d], b0 = bdct[d];
    size_t r2 = (size_t)bd*256+m, r5 = (size_t)bd*512;
    float u = g_u[r2], v = g_v[r2];
    float x0 = g_xt[r5+m], x1 = g_xt[r5+511-m];
    g_z1[r5+m]     = a*(u+v) + c*(g_ce[m]+g_co[m]) + x0*wd + b0;
    g_z1[r5+511-m] = a*(u-v) + c*(g_ce[m]-g_co[m]) + x1*wd + b0;
}

// ---- patch branch: s1 + PN stats ----
__global__ __launch_bounds__(256) void k_patch(){
    __shared__ float xr[512]; __shared__ float ps[32], pq[32];
    int bd = blockIdx.x, tid = threadIdx.x;
    size_t r5 = (size_t)bd*512;
    xr[tid]     = g_xt[r5+tid];
    xr[tid+256] = g_xt[r5+tid+256];
    if(tid<32){ ps[tid]=0.f; pq[tid]=0.f; }
    __syncthreads();
    #pragma unroll
    for(int h=0;h<2;h++){
        int c2 = tid + h*256, n = c2>>4, q = c2&15;
        float s = g_bias2[c2];
        const float* Mr = &g_Mpatch[n*256+q*16];
        const float* xp = &xr[n*16];
        #pragma unroll
        for(int i=0;i<16;i++) s += xp[i]*Mr[i];
        g_s1[r5+c2]=s;
        float sq = s*s;
        #pragma unroll
        for(int o=8;o;o>>=1){ s += __shfl_xor_sync(~0u,s,o); sq += __shfl_xor_sync(~0u,sq,o); }
        if((tid&15)==0){ atomicAdd(&ps[n],s); atomicAdd(&pq[n],sq); }
    }
    __syncthreads();
    if(tid<32){ atomicAdd(&g_stats[PNB+tid],ps[tid]); atomicAdd(&g_stats[PNB+32+tid],pq[tid]); }
}

// ---- z2 = gelu(bn(s1)) with inline PN coeffs; DN stats of conv3(z2) ----
__global__ void k_conv(const float* __restrict__ wdc1, const float* __restrict__ bdc1,
                       const float* __restrict__ gp, const float* __restrict__ bp){
    __shared__ float z2s[512]; __shared__ float ss[32], sq2[32];
    __shared__ float pa[32], pc[32];
    int bd = blockIdx.x, tid = threadIdx.x;
    size_t r5 = (size_t)bd*512;
    if(tid<32){
        ss[tid]=0.f; sq2[tid]=0.f;
        float s=g_stats[PNB+tid], sq=g_stats[PNB+32+tid];
        float m2=s*(1.0f/86016.0f), v2=sq*(1.0f/86016.0f)-m2*m2;
        float aa=gp[tid]*rsqrtf(v2+1e-5f);
        pa[tid]=aa; pc[tid]=bp[tid]-m2*aa;
    }
    __syncthreads();
    #pragma unroll
    for(int h=0;h<2;h++){
        int c = tid + h*256, n = c>>4;
        float g2 = gelu_f(g_s1[r5+c]*pa[n] + pc[n]);
        z2s[c]=g2; g_z2[r5+c]=g2;
    }
    __syncthreads();
    #pragma unroll
    for(int h=0;h<2;h++){
        int c = tid + h*256, n = c>>4, q = c&15;
        float l = q>0 ? z2s[c-1] : 0.f;
        float m0 = z2s[c];
        float r = q<15 ? z2s[c+1] : 0.f;
        float zc = wdc1[n*3+0]*l + wdc1[n*3+1]*m0 + wdc1[n*3+2]*r + bdc1[n];
        float s=zc, sq=zc*zc;
        #pragma unroll
        for(int o=8;o;o>>=1){ s += __shfl_xor_sync(~0u,s,o); sq += __shfl_xor_sync(~0u,sq,o); }
        if((tid&15)==0){ atomicAdd(&ss[n],s); atomicAdd(&sq2[n],sq); }
    }
    __syncthreads();
    if(tid<32){ atomicAdd(&g_stats[DNB+tid],ss[tid]); atomicAdd(&g_stats[DNB+32+tid],sq2[tid]); }
}

// ---- fused: conv3 recompute, z2f with inline DN coeffs, attention dot ----
__global__ void k_z2att(const float* __restrict__ wdc1, const float* __restrict__ bdc1,
                        const float* __restrict__ adwb,
                        const float* __restrict__ gdn, const float* __restrict__ bdn){
    __shared__ float z2s[512]; __shared__ float red[8];
    __shared__ float da[32], dc[32];
    int bd = blockIdx.x, tid = threadIdx.x;
    size_t r5 = (size_t)bd*512;
    z2s[tid]     = g_z2[r5+tid];
    z2s[tid+256] = g_z2[r5+tid+256];
    if(tid<32){
        float s=g_stats[DNB+tid], sq=g_stats[DNB+32+tid];
        float m2=s*(1.0f/86016.0f), v2=sq*(1.0f/86016.0f)-m2*m2;
        float aa=gdn[tid]*rsqrtf(v2+1e-5f);
        da[tid]=aa; dc[tid]=bdn[tid]-m2*aa;
    }
    __syncthreads();
    float dot = 0.f;
    #pragma unroll
    for(int h=0;h<2;h++){
        int c = tid + h*256, n = c>>4, q = c&15;
        float l = q>0 ? z2s[c-1] : 0.f;
        float m0 = z2s[c];
        float r = q<15 ? z2s[c+1] : 0.f;
        float zc = wdc1[n*3+0]*l + wdc1[n*3+1]*m0 + wdc1[n*3+2]*r + bdc1[n];
        float z2f = gelu_f(zc*da[n] + dc[n]) + m0;
        g_z2[r5+c] = z2f;
        dot += g_z1[r5+c]*z2f*g_attcoef[c];
    }
    #pragma unroll
    for(int o=16;o;o>>=1) dot += __shfl_xor_sync(~0u,dot,o);
    if((tid&31)==0) red[tid>>5]=dot;
    __syncthreads();
    if(tid<8){
        float s = red[tid];
        #pragma unroll
        for(int o=4;o;o>>=1) s += __shfl_xor_sync(0xffu,s,o);
        if(tid==0){
            float att = s + adwb[0];
            g_att[bd]=att;
            atomicAdd(&g_stats[ATT_SUM],att);
            atomicAdd(&g_stats[ATT_SQ],att*att);
        }
    }
}

// ---- BN(att) + gelu + softmax over 21 ----
__global__ void k_softmax(const float* __restrict__ ag, const float* __restrict__ ab,
                          const float* __restrict__ cw, const float* __restrict__ cb){
    int b = blockIdx.x, t = threadIdx.x;
    float inv = 1.0f/5376.0f;
    float m = g_stats[ATT_SUM]*inv;
    float v = g_stats[ATT_SQ]*inv - m*m;
    float val = -1e30f;
    if(t<21){
        float a = g_att[b*21+t];
        a = ag[0]*(a-m)*rsqrtf(v+1e-5f)+ab[0];
        a = gelu_f(a);
        val = a*cw[0]+cb[0];
    }
    float mx = val;
    for(int o=16;o;o>>=1) mx = fmaxf(mx,__shfl_xor_sync(~0u,mx,o));
    float e = (t<21) ? expf(val-mx) : 0.f;
    float sum = e;
    for(int o=16;o;o>>=1) sum += __shfl_xor_sync(~0u,sum,o);
    if(t<21) g_att1[b*21+t] = e/sum;
}

extern "C" void kernel_launch(void* const* d_in, const int* in_sizes, int n_in,
                              void* d_out, int out_size){
    const float* x        =(const float*)d_in[0];
    const float* w_dct    =(const float*)d_in[1];
    const float* b_dct    =(const float*)d_in[2];
    const float* W_embed  =(const float*)d_in[3];
    const float* b_embed  =(const float*)d_in[4];
    const float* W_linres =(const float*)d_in[5];
    const float* b_linres =(const float*)d_in[6];
    const float* W_dres   =(const float*)d_in[7];
    const float* b_dres   =(const float*)d_in[8];
    const float* w_dc     =(const float*)d_in[9];
    const float* b_dc     =(const float*)d_in[10];
    const float* w_dc1    =(const float*)d_in[11];
    const float* b_dc1    =(const float*)d_in[12];
    const float* g_dctn   =(const float*)d_in[13];
    const float* b_dctn   =(const float*)d_in[14];
    const float* g_patn   =(const float*)d_in[15];
    const float* b_patn   =(const float*)d_in[16];
    const float* g_depn   =(const float*)d_in[17];
    const float* b_depn   =(const float*)d_in[18];
    const float* thr_p    =(const float*)d_in[19];
    const float* W_m1     =(const float*)d_in[20];
    const float* b_m1     =(const float*)d_in[21];
    const float* W_m2     =(const float*)d_in[22];
    const float* b_m2     =(const float*)d_in[23];
    const float* a_dw_w   =(const float*)d_in[24];
    const float* a_dw_b   =(const float*)d_in[25];
    const float* a_cw     =(const float*)d_in[26];
    const float* a_cb     =(const float*)d_in[27];
    const float* a_g      =(const float*)d_in[28];
    const float* a_b      =(const float*)d_in[29];
    float* out = (float*)d_out;

    float *p_xs,*p_xd,*p_BE,*p_BO,*p_BPe,*p_BPo,*p_zs,*p_u,*p_v,*p_xt,*p_Wf,*p_bL,*p_zr,*p_h;
    cudaGetSymbolAddress((void**)&p_xs,  g_xs);
    cudaGetSymbolAddress((void**)&p_xd,  g_xd);
    cudaGetSymbolAddress((void**)&p_BE,  g_BE);
    cudaGetSymbolAddress((void**)&p_BO,  g_BO);
    cudaGetSymbolAddress((void**)&p_BPe, g_BPe);
    cudaGetSymbolAddress((void**)&p_BPo, g_BPo);
    cudaGetSymbolAddress((void**)&p_zs,  g_zsplit);
    cudaGetSymbolAddress((void**)&p_u,   g_u);
    cudaGetSymbolAddress((void**)&p_v,   g_v);
    cudaGetSymbolAddress((void**)&p_xt,  g_xt);
    cudaGetSymbolAddress((void**)&p_Wf,  g_Wfold);
    cudaGetSymbolAddress((void**)&p_bL,  g_biasL);
    cudaGetSymbolAddress((void**)&p_zr,  g_zres);
    cudaGetSymbolAddress((void**)&p_h,   g_h);

    cudaStream_t s2;
    cudaStreamCreateWithFlags(&s2, cudaStreamNonBlocking);
    cudaEvent_t evA, evM, evT, evJ;
    cudaEventCreateWithFlags(&evA, cudaEventDisableTiming);
    cudaEventCreateWithFlags(&evM, cudaEventDisableTiming);
    cudaEventCreateWithFlags(&evT, cudaEventDisableTiming);
    cudaEventCreateWithFlags(&evJ, cudaEventDisableTiming);

    // Fork s2 into the capture FIRST via an event on the capturing stream.
    cudaEventRecord(evA, 0);
    cudaStreamWaitEvent(s2, evA, 0);

    // side stream: mats + folds
    k_mats<<<257,256,0,s2>>>(a_dw_w, b_linres);
    cudaEventRecord(evM, s2);
    k_fold1n<<<32,256,0,s2>>>(W_embed, W_linres, b_embed);
    k_fold2n<<<32,256,0,s2>>>(W_embed, b_embed, W_dres, b_dres, w_dc, b_dc);

    // main stream: transpose
    k_transpose<<<dim3(256,2),256>>>(x);
    cudaEventRecord(evT, 0);

    // side continues after transpose: patch branch + zres GEMM
    cudaStreamWaitEvent(s2, evT, 0);
    k_patch<<<BD,256,0,s2>>>();
    k_conv<<<BD,256,0,s2>>>(w_dc1,b_dc1,g_patn,b_patn);
    Cfg cW; cW.A=p_xt; cW.B=p_Wf; cW.C=p_zr; cW.bias=p_bL; cW.lda=512; cW.K=512; cW.epi=2; cW.az=0;
    k_gemmB<<<dim3(168,1,1),256,0,s2>>>(cW,nullptr,nullptr);
    cudaEventRecord(evJ, s2);

    // main: DCT chain
    cudaStreamWaitEvent(0, evM, 0);
    k_gemmA<<<dim3(84,2,2),256>>>(p_xs,p_xd,256, p_BE,p_BO, p_zs,p_zs+256,512);
    k_energy<<<672,256>>>();
    k_medquant<<<2,1024>>>(thr_p);
    k_maskgelu<<<BD,256>>>(w_dct,b_dct,thr_p);
    k_gemmA<<<dim3(84,2,2),256>>>(p_zs,p_zs+256,512, p_BPe,p_BPo, p_u,p_v,256);
    k_recombine<<<BD,256>>>(w_dct,b_dct,g_dctn,b_dctn);

    // join
    cudaStreamWaitEvent(0, evJ, 0);
    k_z2att<<<BD,256>>>(w_dc1,b_dc1,a_dw_b,g_depn,b_depn);
    k_softmax<<<256,32>>>(a_g,a_b,a_cw,a_cb);
    Cfg cM1; cM1.A=nullptr; cM1.B=W_m1; cM1.C=p_h; cM1.bias=b_m1; cM1.lda=512; cM1.K=512; cM1.epi=3; cM1.az=1;
    k_gemmB<<<dim3(168,1,1),256>>>(cM1,nullptr,nullptr);
    Cfg cM2; cM2.A=p_h; cM2.B=W_m2; cM2.C=nullptr; cM2.bias=b_m2; cM2.lda=96; cM2.K=96; cM2.epi=4; cM2.az=0;
    k_gemmB<<<dim3(168,1,1),256>>>(cM2,p_zr,out);
}

// round 11
// speedup vs baseline: 1.8069x; 1.0303x over previous
#include <cuda_runtime.h>
#include <cuda_bf16.h>

#define BD 5376
#define CHB 0
#define PNB 128
#define DNB 256
#define ATT_SUM 384
#define ATT_SQ 385
#define PIF 3.14159265358979323846f

typedef unsigned long long ULL;
union F2U { ULL u; float2 f; };

__device__ float g_BE[65536], g_BO[65536], g_BPe[65536], g_BPo[65536];
__device__ float g_ce[256], g_co[256], g_attcoef[512];
__device__ float g_Wfold[49152], g_biasL[96], g_Mpatch[8192], g_bias2[512];
__device__ float g_xt[BD*512], g_xs[BD*256], g_xd[BD*256];
__device__ float g_zsplit[BD*512], g_u[BD*256], g_v[BD*256], g_z1[BD*512];
__device__ float g_s1[BD*512], g_z2[BD*512];
__device__ float g_zres[BD*96], g_h[BD*96];
__device__ float g_epart[4*BD], g_norme[BD], g_att[BD], g_att1[BD];
__device__ float g_thr[2], g_stats[512];

__device__ __forceinline__ float gelu_f(float x){
    return 0.5f*x*(1.0f+erff(x*0.70710678118654752440f));
}
__device__ __forceinline__ ULL dup2(float x){ ULL r; asm("mov.b64 %0,{%1,%1};":"=l"(r):"f"(x)); return r; }
#define FFMA2(d,a,b) asm("fma.rn.f32x2 %0, %1, %2, %0;" : "+l"(d) : "l"(a), "l"(b))

// ---- DCT matrices + attcoef + stats zero + biasL init ----
__global__ void k_mats(const float* __restrict__ adw, const float* __restrict__ bl){
    int bm = blockIdx.x, t = threadIdx.x;
    if(bm < 256){
        int m = bm, j = t;
        float am = PIF*(float)(2*m+1);
        float ce = cosf(am*(float)(2*j)*(1.0f/1024.0f));
        float co = cosf(am*(float)(2*j+1)*(1.0f/1024.0f));
        g_BE[m*256+j] = 2.0f*ce;
        g_BO[m*256+j] = 2.0f*co;
        float bpe = ce*((j==0)?0.5f:1.0f)*(1.0f/512.0f);
        float bpo = co*(1.0f/512.0f);
        g_BPe[j*256+m] = bpe;
        g_BPo[j*256+m] = bpo;
        __shared__ float r1[256], r2[256];
        r1[t]=bpe; r2[t]=bpo; __syncthreads();
        for(int o=128;o>0;o>>=1){ if(t<o){ r1[t]+=r1[t+o]; r2[t]+=r2[t+o]; } __syncthreads(); }
        if(t==0){ g_ce[m]=r1[0]; g_co[m]=r2[0]; }
    } else {
        float rL = sqrtf(512.0f);
        for(int m=t; m<512; m+=256){
            float am = PIF*(float)(2*m+1);
            float s = 0.f;
            for(int k=0;k<5;k++){
                float c = 2.0f*cosf(am*(float)k*(1.0f/1024.0f));
                float so = (k==0)? (0.5f/rL) : (0.5f*sqrtf(2.0f)/rL);
                s += adw[k]*so*c;
            }
            g_attcoef[m]=s;
        }
        g_stats[t]=0.f; g_stats[t+256]=0.f;
        if(t<96) g_biasL[t]=bl[t];
    }
}

// ---- fold1: Wfold + biasL ----
__global__ __launch_bounds__(256) void k_fold1n(const float* __restrict__ We,
        const float* __restrict__ Wl, const float* __restrict__ be){
    __shared__ float sWe[4096];
    __shared__ float sbe[256];
    __shared__ float sWl[32][100];
    int n = blockIdx.x, tid = threadIdx.x;
    for(int i=tid;i<4096;i+=256) sWe[i]=We[i];
    sbe[tid]=be[tid];
    int pp = tid>>5, ts = tid&31;
    float acc[2][3] = {};
    float accb = 0.f;
    for(int k0=0;k0<256;k0+=32){
        __syncthreads();
        for(int i2=tid;i2<32*96;i2+=256){
            int r=i2/96, c2=i2-r*96;
            sWl[r][c2]=Wl[(size_t)(n*256+k0+r)*96+c2];
        }
        __syncthreads();
        #pragma unroll
        for(int kk=0;kk<32;kk++){
            float a0=sWe[pp*256+k0+kk], a1=sWe[(pp+8)*256+k0+kk];
            float b0=sWl[kk][ts], b1=sWl[kk][ts+32], b2=sWl[kk][ts+64];
            acc[0][0]+=a0*b0; acc[0][1]+=a0*b1; acc[0][2]+=a0*b2;
            acc[1][0]+=a1*b0; acc[1][1]+=a1*b1; acc[1][2]+=a1*b2;
            if(tid<96) accb += sbe[k0+kk]*sWl[kk][tid];
        }
    }
    #pragma unroll
    for(int e=0;e<2;e++){
        int p = pp + e*8;
        int base = (n*16+p)*96;
        g_Wfold[base+ts]    = acc[e][0];
        g_Wfold[base+ts+32] = acc[e][1];
        g_Wfold[base+ts+64] = acc[e][2];
    }
    if(tid<96) atomicAdd(&g_biasL[tid], accb);
}

// ---- fold2: Mpatch + bias2 ----
__global__ __launch_bounds__(256) void k_fold2n(const float* __restrict__ We,
        const float* __restrict__ be, const float* __restrict__ Wd,
        const float* __restrict__ bdres, const float* __restrict__ wdc,
        const float* __restrict__ bdc){
    __shared__ float sWe[16*257];
    __shared__ float sWd[16*257];
    __shared__ float swdc[16];
    int n = blockIdx.x, tid = threadIdx.x;
    for(int i2=tid;i2<4096;i2+=256){
        int r=i2>>8, c2=i2&255;
        sWe[r*257+c2]=We[i2];
        int j=i2>>4, q=i2&15;
        sWd[q*257+j]=Wd[i2];
    }
    if(tid<16) swdc[tid]=wdc[n*16+tid];
    __syncthreads();
    int i=tid&15, q=tid>>4;
    float s=0.f;
    #pragma unroll
    for(int p=0;p<16;p++) s += sWe[i*257+q*16+p]*swdc[p];
    for(int j=0;j<256;j++) s += sWe[i*257+j]*sWd[q*257+j];
    g_Mpatch[n*256+q*16+i]=s;
    if(tid<16){
        int qq=tid;
        float b=bdc[n]+bdres[qq];
        #pragma unroll
        for(int p=0;p<16;p++) b += be[qq*16+p]*swdc[p];
        for(int j=0;j<256;j++) b += be[j]*sWd[qq*257+j];
        g_bias2[n*16+qq]=b;
    }
}

// ---- transpose + symmetric split ----
__global__ __launch_bounds__(256) void k_transpose(const float* __restrict__ x){
    __shared__ float sa[128*21], sb[128*21];
    int b = blockIdx.x, c = blockIdx.y, tid = threadIdx.x;
    int l0 = c*128, l1 = (3-c)*128;
    const float* xb = x + (size_t)b*512*21;
    for(int i=tid;i<128*21;i+=256){ sa[i]=xb[l0*21+i]; sb[i]=xb[l1*21+i]; }
    __syncthreads();
    int t = tid&127;
    for(int d=(tid>>7); d<21; d+=2){
        size_t row = (size_t)(b*21+d);
        float va = sa[t*21+d], vb = sb[(127-t)*21+d], vb2 = sb[t*21+d];
        g_xt[row*512+l0+t]=va;
        g_xt[row*512+l1+t]=vb2;
        g_xs[row*256+l0+t]=va+vb;
        g_xd[row*256+l0+t]=va-vb;
    }
}

// ---- DCT GEMM: M64 x N128, K=256 ----
// MODE 0: forward — plain A load; epilogue stores C and row-energy partials (deterministic).
// MODE 1: inverse — A-load applies mask+scale+gelu; y==0 blocks accumulate CH BN stats.
template<int MODE>
__global__ __launch_bounds__(256,3) void k_gemmA(
    const float* __restrict__ A0, const float* __restrict__ A1, int lda,
    const float* __restrict__ B0, const float* __restrict__ B1,
    float* __restrict__ C0, float* __restrict__ C1, int ldc,
    const float* __restrict__ wdct, const float* __restrict__ bdct,
    const float* __restrict__ thr_p)
{
    const float* A  = blockIdx.z ? A1 : A0;
    const float* Bm = blockIdx.z ? B1 : B0;
    float* C        = blockIdx.z ? C1 : C0;
    __shared__ float As[16][66];
    __shared__ __align__(16) float Bs[16][128];
    int row0 = blockIdx.x*64, col0 = blockIdx.y*128;
    int tid = threadIdx.x, tx = tid&31, ty = tid>>5;
    int am = tid&63, ak = (tid>>6)*4;
    int bn = (tid&31)*4, bk = tid>>5;
    ULL acc[4][4] = {};
    float wdm=0.f, bb=0.f, ls=0.f, lq=0.f;
    if(MODE==1){
        int row = row0+am, d = row - (row/21)*21;
        float pos = thr_p[0]*5375.0f;
        float fr = pos - floorf(pos);
        float thr = g_thr[0] + fr*(g_thr[1]-g_thr[0]);
        float msk = (g_norme[row] > thr) ? 1.f : 0.f;
        wdm = wdct[d]*msk; bb = bdct[d];
    }
    for(int kc=0;kc<256;kc+=16){
        float4 a4 = *(const float4*)&A[(size_t)(row0+am)*lda + kc + ak];
        if(MODE==1){
            a4.x = gelu_f(a4.x*wdm + bb);
            a4.y = gelu_f(a4.y*wdm + bb);
            a4.z = gelu_f(a4.z*wdm + bb);
            a4.w = gelu_f(a4.w*wdm + bb);
            if(blockIdx.y==0){
                ls += a4.x+a4.y+a4.z+a4.w;
                lq += a4.x*a4.x+a4.y*a4.y+a4.z*a4.z+a4.w*a4.w;
            }
        }
        As[ak+0][am]=a4.x; As[ak+1][am]=a4.y; As[ak+2][am]=a4.z; As[ak+3][am]=a4.w;
        float4 b0 = *(const float4*)&Bm[(size_t)(kc+bk)*256 + col0 + bn];
        float4 b1 = *(const float4*)&Bm[(size_t)(kc+bk+8)*256 + col0 + bn];
        *(float4*)&Bs[bk][bn]   = b0;
        *(float4*)&Bs[bk+8][bn] = b1;
        __syncthreads();
        #pragma unroll
        for(int k=0;k<16;k++){
            ULL av[4];
            #pragma unroll
            for(int rp=0;rp<4;rp++) av[rp] = *(const ULL*)&As[k][ty*8+2*rp];
            float4 bx = *(const float4*)&Bs[k][tx*4];
            ULL bd0=dup2(bx.x), bd1=dup2(bx.y), bd2=dup2(bx.z), bd3=dup2(bx.w);
            #pragma unroll
            for(int rp=0;rp<4;rp++){
                FFMA2(acc[rp][0],av[rp],bd0);
                FFMA2(acc[rp][1],av[rp],bd1);
                FFMA2(acc[rp][2],av[rp],bd2);
                FFMA2(acc[rp][3],av[rp],bd3);
            }
        }
        __syncthreads();
    }
    int col = col0 + tx*4;
    #pragma unroll
    for(int rp=0;rp<4;rp++){
        int r = row0 + ty*8 + 2*rp;
        F2U t0,t1,t2,t3; t0.u=acc[rp][0]; t1.u=acc[rp][1]; t2.u=acc[rp][2]; t3.u=acc[rp][3];
        float4 lo = make_float4(t0.f.x,t1.f.x,t2.f.x,t3.f.x);
        float4 hi = make_float4(t0.f.y,t1.f.y,t2.f.y,t3.f.y);
        *(float4*)&C[(size_t)r*ldc + col]     = lo;
        *(float4*)&C[(size_t)(r+1)*ldc + col] = hi;
        if(MODE==0){
            // deterministic row-energy partials (128 cols in this block)
            float elo = lo.x*lo.x + lo.y*lo.y + lo.z*lo.z + lo.w*lo.w;
            float ehi = hi.x*hi.x + hi.y*hi.y + hi.z*hi.z + hi.w*hi.w;
            #pragma unroll
            for(int o=16;o;o>>=1){
                elo += __shfl_xor_sync(~0u,elo,o);
                ehi += __shfl_xor_sync(~0u,ehi,o);
            }
            if(tx==0){
                int slot = (blockIdx.y*2 + blockIdx.z)*BD;
                g_epart[slot + r]   = elo;
                g_epart[slot + r+1] = ehi;
            }
        }
    }
    if(MODE==1 && blockIdx.y==0){
        __shared__ float rs1[64], rs2[64];
        if(tid<64){ rs1[tid]=0.f; rs2[tid]=0.f; }
        __syncthreads();
        atomicAdd(&rs1[am], ls);
        atomicAdd(&rs2[am], lq);
        __syncthreads();
        if(tid<64){
            int row = row0+tid, d = row - (row/21)*21;
            atomicAdd(&g_stats[CHB+d],    rs1[tid]);
            atomicAdd(&g_stats[CHB+32+d], rs2[tid]);
        }
    }
}

// ---- Output GEMM: M32 x N96(padded 128) ----
struct Cfg { const float* A; const float* B; float* C; const float* bias;
             int lda; int K; int epi; int az; };

__global__ __launch_bounds__(256,4) void k_gemmB(Cfg c0,
        const float* __restrict__ addp, float* __restrict__ outp)
{
    Cfg c = c0;
    __shared__ float As[16][34];
    __shared__ __align__(16) float Bs[16][128];
    int row0 = blockIdx.x*32;
    int tid = threadIdx.x, tx = tid&31, ty = tid>>5;
    int am = tid&31, ak = (tid>>5)*2;
    int bn = (tid&31)*4, bk = tid>>5;
    ULL acc[2][4] = {};
    float w = 0.f;
    if(c.az) w = g_att1[row0+am];
    for(int kc=0;kc<c.K;kc+=16){
        float2 a2;
        if(c.az){
            size_t o = (size_t)(row0+am)*512 + kc + ak;
            float2 z1v = *(const float2*)&g_z1[o];
            float2 z2v = *(const float2*)&g_z2[o];
            a2.x = z1v.x*w + z2v.x*(1.0f-w);
            a2.y = z1v.y*w + z2v.y*(1.0f-w);
        } else {
            a2 = *(const float2*)&c.A[(size_t)(row0+am)*c.lda + kc + ak];
        }
        As[ak][am]=a2.x; As[ak+1][am]=a2.y;
        float4 b0 = make_float4(0.f,0.f,0.f,0.f), b1 = b0;
        if(bn<96){
            b0 = *(const float4*)&c.B[(size_t)(kc+bk)*96 + bn];
            b1 = *(const float4*)&c.B[(size_t)(kc+bk+8)*96 + bn];
        }
        *(float4*)&Bs[bk][bn]   = b0;
        *(float4*)&Bs[bk+8][bn] = b1;
        __syncthreads();
        #pragma unroll
        for(int k=0;k<16;k++){
            ULL av0 = *(const ULL*)&As[k][ty*4];
            ULL av1 = *(const ULL*)&As[k][ty*4+2];
            float4 bx = *(const float4*)&Bs[k][tx*4];
            ULL bd0=dup2(bx.x), bd1=dup2(bx.y), bd2=dup2(bx.z), bd3=dup2(bx.w);
            FFMA2(acc[0][0],av0,bd0); FFMA2(acc[0][1],av0,bd1);
            FFMA2(acc[0][2],av0,bd2); FFMA2(acc[0][3],av0,bd3);
            FFMA2(acc[1][0],av1,bd0); FFMA2(acc[1][1],av1,bd1);
            FFMA2(acc[1][2],av1,bd2); FFMA2(acc[1][3],av1,bd3);
        }
        __syncthreads();
    }
    int col = tx*4;
    if(col<96){
        #pragma unroll
        for(int rp=0;rp<2;rp++){
            int r = row0 + ty*4 + 2*rp;
            F2U t0,t1,t2,t3; t0.u=acc[rp][0]; t1.u=acc[rp][1]; t2.u=acc[rp][2]; t3.u=acc[rp][3];
            float vlo[4]={t0.f.x,t1.f.x,t2.f.x,t3.f.x};
            float vhi[4]={t0.f.y,t1.f.y,t2.f.y,t3.f.y};
            #pragma unroll
            for(int e=0;e<2;e++){
                int row = r+e;
                #pragma unroll
                for(int j=0;j<4;j++){
                    float v = (e? vhi[j] : vlo[j]) + c.bias[col+j];
                    if(c.epi==3) v = gelu_f(v);
                    if(c.epi==4){
                        v += addp[(size_t)row*96+col+j];
                        int b = row/21, d = row - b*21;
                        outp[(size_t)b*2016 + (col+j)*21 + d] = v;
                    } else {
                        c.C[(size_t)row*96+col+j] = v;
                    }
                }
            }
        }
    }
}

// ---- fused median + global quantile radix select (parallel bucket scan); 2 blocks ----
__global__ __launch_bounds__(1024) void k_medquant(const float* __restrict__ thr_p){
    __shared__ float e[5376]; __shared__ float med[256];
    __shared__ unsigned vals[5376];
    __shared__ unsigned hist[256];
    __shared__ unsigned s_pref; __shared__ int s_r;
    int tid = threadIdx.x;
    for(int i=tid;i<5376;i+=1024)
        e[i] = ((g_epart[i] + g_epart[BD+i]) + g_epart[2*BD+i]) + g_epart[3*BD+i];
    __syncthreads();
    if(tid<256){
        int b0 = tid*21;
        float m=0.f;
        for(int j=0;j<21;j++){
            float xj=e[b0+j]; int less=0,eq=0;
            for(int k2=0;k2<21;k2++){ float y=e[b0+k2]; less+=(y<xj); eq+=(y==xj); }
            if(less<=10 && 10<less+eq) m=xj;
        }
        med[tid]=m;
    }
    __syncthreads();
    for(int i=tid;i<5376;i+=1024){
        float nm = e[i]/(med[i/21]+1e-6f);
        vals[i]=__float_as_uint(nm);
        if(blockIdx.x==0) g_norme[i]=nm;
    }
    float pos = thr_p[0]*5375.0f;
    int i0 = (int)floorf(pos);
    int r = blockIdx.x ? ((i0+1<5376)?i0+1:5375) : i0;
    unsigned prefix=0, msk=0;
    for(int shift=24;shift>=0;shift-=8){
        if(tid<256) hist[tid]=0;
        __syncthreads();
        for(int i=tid;i<5376;i+=1024){
            unsigned xv=vals[i];
            if((xv&msk)==prefix) atomicAdd(&hist[(xv>>shift)&255],1u);
        }
        __syncthreads();
        for(int o=1;o<256;o<<=1){
            unsigned y=0;
            if(tid<256 && tid>=(unsigned)o) y=hist[tid-o];
            __syncthreads();
            if(tid<256) hist[tid]+=y;
            __syncthreads();
        }
        if(tid<256){
            unsigned lo = tid? hist[tid-1]:0u, hi=hist[tid];
            if(lo<=(unsigned)r && (unsigned)r<hi){ s_pref=prefix|((unsigned)tid<<shift); s_r=r-(int)lo; }
        }
        __syncthreads();
        prefix=s_pref; r=s_r; msk|=(255u<<shift);
        __syncthreads();
    }
    if(tid==0) g_thr[blockIdx.x]=__uint_as_float(prefix);
}

// ---- recombine inverse-DCT + inline CH BN + residual ----
__global__ __launch_bounds__(256) void k_recombine(const float* __restrict__ wdct,
        const float* __restrict__ bdct, const float* __restrict__ gd,
        const float* __restrict__ bD){
    int bd = blockIdx.x, m = threadIdx.x;
    int d = bd - (bd/21)*21;
    float s = g_stats[CHB+d], sq = g_stats[CHB+32+d];
    float mm = s*(1.0f/131072.0f), vv = sq*(1.0f/131072.0f)-mm*mm;
    float a = gd[d]*rsqrtf(vv+1e-5f);
    float c = bD[d]-mm*a;
    float wd = wdct[d], b0 = bdct[d];
    size_t r2 = (size_t)bd*256+m, r5 = (size_t)bd*512;
    float u = g_u[r2], v = g_v[r2];
    float x0 = g_xt[r5+m], x1 = g_xt[r5+511-m];
    g_z1[r5+m]     = a*(u+v) + c*(g_ce[m]+g_co[m]) + x0*wd + b0;
    g_z1[r5+511-m] = a*(u-v) + c*(g_ce[m]-g_co[m]) + x1*wd + b0;
}

// ---- patch branch: s1 + PN stats ----
__global__ __launch_bounds__(256) void k_patch(){
    __shared__ float xr[512]; __shared__ float ps[32], pq[32];
    int bd = blockIdx.x, tid = threadIdx.x;
    size_t r5 = (size_t)bd*512;
    xr[tid]     = g_xt[r5+tid];
    xr[tid+256] = g_xt[r5+tid+256];
    if(tid<32){ ps[tid]=0.f; pq[tid]=0.f; }
    __syncthreads();
    #pragma unroll
    for(int h=0;h<2;h++){
        int c2 = tid + h*256, n = c2>>4, q = c2&15;
        float s = g_bias2[c2];
        const float* Mr = &g_Mpatch[n*256+q*16];
        const float* xp = &xr[n*16];
        #pragma unroll
        for(int i=0;i<16;i++) s += xp[i]*Mr[i];
        g_s1[r5+c2]=s;
        float sq = s*s;
        #pragma unroll
        for(int o=8;o;o>>=1){ s += __shfl_xor_sync(~0u,s,o); sq += __shfl_xor_sync(~0u,sq,o); }
        if((tid&15)==0){ atomicAdd(&ps[n],s); atomicAdd(&pq[n],sq); }
    }
    __syncthreads();
    if(tid<32){ atomicAdd(&g_stats[PNB+tid],ps[tid]); atomicAdd(&g_stats[PNB+32+tid],pq[tid]); }
}

// ---- z2 = gelu(bn(s1)) with inline PN coeffs; DN stats of conv3(z2) ----
__global__ void k_conv(const float* __restrict__ wdc1, const float* __restrict__ bdc1,
                       const float* __restrict__ gp, const float* __restrict__ bp){
    __shared__ float z2s[512]; __shared__ float ss[32], sq2[32];
    __shared__ float pa[32], pc[32];
    int bd = blockIdx.x, tid = threadIdx.x;
    size_t r5 = (size_t)bd*512;
    if(tid<32){
        ss[tid]=0.f; sq2[tid]=0.f;
        float s=g_stats[PNB+tid], sq=g_stats[PNB+32+tid];
        float m2=s*(1.0f/86016.0f), v2=sq*(1.0f/86016.0f)-m2*m2;
        float aa=gp[tid]*rsqrtf(v2+1e-5f);
        pa[tid]=aa; pc[tid]=bp[tid]-m2*aa;
    }
    __syncthreads();
    #pragma unroll
    for(int h=0;h<2;h++){
        int c = tid + h*256, n = c>>4;
        float g2 = gelu_f(g_s1[r5+c]*pa[n] + pc[n]);
        z2s[c]=g2; g_z2[r5+c]=g2;
    }
    __syncthreads();
    #pragma unroll
    for(int h=0;h<2;h++){
        int c = tid + h*256, n = c>>4, q = c&15;
        float l = q>0 ? z2s[c-1] : 0.f;
        float m0 = z2s[c];
        float r = q<15 ? z2s[c+1] : 0.f;
        float zc = wdc1[n*3+0]*l + wdc1[n*3+1]*m0 + wdc1[n*3+2]*r + bdc1[n];
        float s=zc, sq=zc*zc;
        #pragma unroll
        for(int o=8;o;o>>=1){ s += __shfl_xor_sync(~0u,s,o); sq += __shfl_xor_sync(~0u,sq,o); }
        if((tid&15)==0){ atomicAdd(&ss[n],s); atomicAdd(&sq2[n],sq); }
    }
    __syncthreads();
    if(tid<32){ atomicAdd(&g_stats[DNB+tid],ss[tid]); atomicAdd(&g_stats[DNB+32+tid],sq2[tid]); }
}

// ---- fused: conv3 recompute, z2f with inline DN coeffs, attention dot ----
__global__ void k_z2att(const float* __restrict__ wdc1, const float* __restrict__ bdc1,
                        const float* __restrict__ adwb,
                        const float* __restrict__ gdn, const float* __restrict__ bdn){
    __shared__ float z2s[512]; __shared__ float red[8];
    __shared__ float da[32], dc[32];
    int bd = blockIdx.x, tid = threadIdx.x;
    size_t r5 = (size_t)bd*512;
    z2s[tid]     = g_z2[r5+tid];
    z2s[tid+256] = g_z2[r5+tid+256];
    if(tid<32){
        float s=g_stats[DNB+tid], sq=g_stats[DNB+32+tid];
        float m2=s*(1.0f/86016.0f), v2=sq*(1.0f/86016.0f)-m2*m2;
        float aa=gdn[tid]*rsqrtf(v2+1e-5f);
        da[tid]=aa; dc[tid]=bdn[tid]-m2*aa;
    }
    __syncthreads();
    float dot = 0.f;
    #pragma unroll
    for(int h=0;h<2;h++){
        int c = tid + h*256, n = c>>4, q = c&15;
        float l = q>0 ? z2s[c-1] : 0.f;
        float m0 = z2s[c];
        float r = q<15 ? z2s[c+1] : 0.f;
        float zc = wdc1[n*3+0]*l + wdc1[n*3+1]*m0 + wdc1[n*3+2]*r + bdc1[n];
        float z2f = gelu_f(zc*da[n] + dc[n]) + m0;
        g_z2[r5+c] = z2f;
        dot += g_z1[r5+c]*z2f*g_attcoef[c];
    }
    #pragma unroll
    for(int o=16;o;o>>=1) dot += __shfl_xor_sync(~0u,dot,o);
    if((tid&31)==0) red[tid>>5]=dot;
    __syncthreads();
    if(tid<8){
        float s = red[tid];
        #pragma unroll
        for(int o=4;o;o>>=1) s += __shfl_xor_sync(0xffu,s,o);
        if(tid==0){
            float att = s + adwb[0];
            g_att[bd]=att;
            atomicAdd(&g_stats[ATT_SUM],att);
            atomicAdd(&g_stats[ATT_SQ],att*att);
        }
    }
}

// ---- BN(att) + gelu + softmax over 21 ----
__global__ void k_softmax(const float* __restrict__ ag, const float* __restrict__ ab,
                          const float* __restrict__ cw, const float* __restrict__ cb){
    int b = blockIdx.x, t = threadIdx.x;
    float inv = 1.0f/5376.0f;
    float m = g_stats[ATT_SUM]*inv;
    float v = g_stats[ATT_SQ]*inv - m*m;
    float val = -1e30f;
    if(t<21){
        float a = g_att[b*21+t];
        a = ag[0]*(a-m)*rsqrtf(v+1e-5f)+ab[0];
        a = gelu_f(a);
        val = a*cw[0]+cb[0];
    }
    float mx = val;
    for(int o=16;o;o>>=1) mx = fmaxf(mx,__shfl_xor_sync(~0u,mx,o));
    float e = (t<21) ? expf(val-mx) : 0.f;
    float sum = e;
    for(int o=16;o;o>>=1) sum += __shfl_xor_sync(~0u,sum,o);
    if(t<21) g_att1[b*21+t] = e/sum;
}

extern "C" void kernel_launch(void* const* d_in, const int* in_sizes, int n_in,
                              void* d_out, int out_size){
    const float* x        =(const float*)d_in[0];
    const float* w_dct    =(const float*)d_in[1];
    const float* b_dct    =(const float*)d_in[2];
    const float* W_embed  =(const float*)d_in[3];
    const float* b_embed  =(const float*)d_in[4];
    const float* W_linres =(const float*)d_in[5];
    const float* b_linres =(const float*)d_in[6];
    const float* W_dres   =(const float*)d_in[7];
    const float* b_dres   =(const float*)d_in[8];
    const float* w_dc     =(const float*)d_in[9];
    const float* b_dc     =(const float*)d_in[10];
    const float* w_dc1    =(const float*)d_in[11];
    const float* b_dc1    =(const float*)d_in[12];
    const float* g_dctn   =(const float*)d_in[13];
    const float* b_dctn   =(const float*)d_in[14];
    const float* g_patn   =(const float*)d_in[15];
    const float* b_patn   =(const float*)d_in[16];
    const float* g_depn   =(const float*)d_in[17];
    const float* b_depn   =(const float*)d_in[18];
    const float* thr_p    =(const float*)d_in[19];
    const float* W_m1     =(const float*)d_in[20];
    const float* b_m1     =(const float*)d_in[21];
    const float* W_m2     =(const float*)d_in[22];
    const float* b_m2     =(const float*)d_in[23];
    const float* a_dw_w   =(const float*)d_in[24];
    const float* a_dw_b   =(const float*)d_in[25];
    const float* a_cw     =(const float*)d_in[26];
    const float* a_cb     =(const float*)d_in[27];
    const float* a_g      =(const float*)d_in[28];
    const float* a_b      =(const float*)d_in[29];
    float* out = (float*)d_out;

    float *p_xs,*p_xd,*p_BE,*p_BO,*p_BPe,*p_BPo,*p_zs,*p_u,*p_v,*p_xt,*p_Wf,*p_bL,*p_zr,*p_h;
    cudaGetSymbolAddress((void**)&p_xs,  g_xs);
    cudaGetSymbolAddress((void**)&p_xd,  g_xd);
    cudaGetSymbolAddress((void**)&p_BE,  g_BE);
    cudaGetSymbolAddress((void**)&p_BO,  g_BO);
    cudaGetSymbolAddress((void**)&p_BPe, g_BPe);
    cudaGetSymbolAddress((void**)&p_BPo, g_BPo);
    cudaGetSymbolAddress((void**)&p_zs,  g_zsplit);
    cudaGetSymbolAddress((void**)&p_u,   g_u);
    cudaGetSymbolAddress((void**)&p_v,   g_v);
    cudaGetSymbolAddress((void**)&p_xt,  g_xt);
    cudaGetSymbolAddress((void**)&p_Wf,  g_Wfold);
    cudaGetSymbolAddress((void**)&p_bL,  g_biasL);
    cudaGetSymbolAddress((void**)&p_zr,  g_zres);
    cudaGetSymbolAddress((void**)&p_h,   g_h);

    cudaStream_t s2;
    cudaStreamCreateWithFlags(&s2, cudaStreamNonBlocking);
    cudaEvent_t evA, evM, evT, evJ;
    cudaEventCreateWithFlags(&evA, cudaEventDisableTiming);
    cudaEventCreateWithFlags(&evM, cudaEventDisableTiming);
    cudaEventCreateWithFlags(&evT, cudaEventDisableTiming);
    cudaEventCreateWithFlags(&evJ, cudaEventDisableTiming);

    // Fork s2 into the capture FIRST via an event on the capturing stream.
    cudaEventRecord(evA, 0);
    cudaStreamWaitEvent(s2, evA, 0);

    // side stream: mats + folds
    k_mats<<<257,256,0,s2>>>(a_dw_w, b_linres);
    cudaEventRecord(evM, s2);
    k_fold1n<<<32,256,0,s2>>>(W_embed, W_linres, b_embed);
    k_fold2n<<<32,256,0,s2>>>(W_embed, b_embed, W_dres, b_dres, w_dc, b_dc);

    // main stream: transpose
    k_transpose<<<dim3(256,2),256>>>(x);
    cudaEventRecord(evT, 0);

    // side continues after transpose: patch branch + zres GEMM
    cudaStreamWaitEvent(s2, evT, 0);
    k_patch<<<BD,256,0,s2>>>();
    k_conv<<<BD,256,0,s2>>>(w_dc1,b_dc1,g_patn,b_patn);
    Cfg cW; cW.A=p_xt; cW.B=p_Wf; cW.C=p_zr; cW.bias=p_bL; cW.lda=512; cW.K=512; cW.epi=2; cW.az=0;
    k_gemmB<<<dim3(168,1,1),256,0,s2>>>(cW,nullptr,nullptr);
    cudaEventRecord(evJ, s2);

    // main: DCT chain (forward GEMM + fused energy; medquant; inverse GEMM + fused mask/gelu/stats)
    cudaStreamWaitEvent(0, evM, 0);
    k_gemmA<0><<<dim3(84,2,2),256>>>(p_xs,p_xd,256, p_BE,p_BO, p_zs,p_zs+256,512,
                                     nullptr,nullptr,nullptr);
    k_medquant<<<2,1024>>>(thr_p);
    k_gemmA<1><<<dim3(84,2,2),256>>>(p_zs,p_zs+256,512, p_BPe,p_BPo, p_u,p_v,256,
                                     w_dct,b_dct,thr_p);
    k_recombine<<<BD,256>>>(w_dct,b_dct,g_dctn,b_dctn);

    // join
    cudaStreamWaitEvent(0, evJ, 0);
    k_z2att<<<BD,256>>>(w_dc1,b_dc1,a_dw_b,g_depn,b_depn);
    k_softmax<<<256,32>>>(a_g,a_b,a_cw,a_cb);
    Cfg cM1; cM1.A=nullptr; cM1.B=W_m1; cM1.C=p_h; cM1.bias=b_m1; cM1.lda=512; cM1.K=512; cM1.epi=3; cM1.az=1;
    k_gemmB<<<dim3(168,1,1),256>>>(cM1,nullptr,nullptr);
    Cfg cM2; cM2.A=p_h; cM2.B=W_m2; cM2.C=nullptr; cM2.bias=b_m2; cM2.lda=96; cM2.K=96; cM2.epi=4; cM2.az=0;
    k_gemmB<<<dim3(168,1,1),256>>>(cM2,p_zr,out);
}